// round 17
// baseline (speedup 1.0000x reference)
#include <cuda_runtime.h>
#include <math.h>

typedef unsigned long long ull;

#define BDIM 2
#define NTOT 1024
#define PLEN 768
#define LLEN 256
#define KDIM 128
#define HDIM 32
#define TABN 8192

constexpr int PP = 132;
constexpr int NT_LP = BDIM * PLEN * 4;           // 6144
constexpr int NT_LL_SLOW = BDIM * LLEN * 4;      // 2048
constexpr int NTILES_SLOW = NT_LL_SLOW + NT_LP;  // 8192
constexpr int NT_LL_FAST = BDIM * 640;           // 1280
constexpr int NTILES_FAST = NT_LL_FAST + NT_LP;  // 7424
constexpr int NTAB_TILES = TABN / 64;            // 128

constexpr int GRIDX = 148;
constexpr int GRIDF = 296;
constexpr int ZTOT_F4 = BDIM * HDIM * PLEN * (PLEN / 4);   // 9437184
constexpr int NZI  = (ZTOT_F4 + 3 * GRIDX * 512 - 1) / (3 * GRIDX * 512);  // 42
constexpr int NZIF = (ZTOT_F4 + 3 * GRIDF * 512 - 1) / (3 * GRIDF * 512);  // 21

constexpr int NTT_PER_BH = 216;
constexpr int NTT_TOTAL  = NTT_PER_BH * BDIM * HDIM;   // 13824

// ---------- big-smem layout (exact + build kernels) ----------
constexpr int OFF_OW1  = 0;
constexpr int OFF_OW2  = 16384;
constexpr int OFF_VW2  = 20480;
constexpr int OFF_TVV  = 24576;
constexpr int OFF_VW1  = 24672;
constexpr int OFF_VB1  = 25056;
constexpr int OFF_OB1  = 25184;
constexpr int OFF_MEAN = 25312;
constexpr int OFF_ISTD = 25440;
constexpr int OFF_COEF = 25568;
constexpr int OFF_B2   = 25696;
constexpr int OFF_FLAG = 25728;
constexpr int OFF_DLM4 = 25732;
constexpr int OFF_GP   = 26244;
constexpr int OFF_VP1  = OFF_GP + 64 * PP;       // 34692
constexpr int OFF_H1P  = OFF_VP1 + 64 * PP;      // 43140
constexpr int SCP = 36;
constexpr int SCSTRIDE = 64 * SCP;               // 2304
constexpr int OFF_SCR  = OFF_H1P + 64 * PP;      // 51588
constexpr int SMEM_FLOATS = OFF_SCR + SCSTRIDE;  // 53892
constexpr int SMEM_BYTES  = SMEM_FLOATS * 4;     // 215568

// ---------- slim layout (fast kernel); VP1 double-buffered ----------
constexpr int F_VW2  = 0;                        // 4096
constexpr int F_VW1  = 4096;                     // 384
constexpr int F_B2   = 4480;                     // 32
constexpr int F_DLM4 = 4512;                     // 512 (2 buffers)
constexpr int F_VP1  = 5024;                     // 2 x 8448
constexpr int FSMEM_FLOATS = F_VP1 + 2 * 64 * PP;  // 21920
constexpr int FSMEM_BYTES  = FSMEM_FLOATS * 4;     // 87680

__device__ __align__(16) float g_tab[TABN * HDIM];
__device__ __align__(16) float g_T3[96];
__device__ int g_flags;

__device__ __forceinline__ ull ffma2(ull a, ull b, ull c) {
    ull d; asm("fma.rn.f32x2 %0,%1,%2,%3;" : "=l"(d) : "l"(a), "l"(b), "l"(c)); return d;
}
__device__ __forceinline__ float2 u2f2(ull v) {
    float2 f; asm("mov.b64 {%0,%1},%2;" : "=f"(f.x), "=f"(f.y) : "l"(v)); return f;
}
__device__ __forceinline__ ull f2pack(float x, float y) {
    ull r; asm("mov.b64 %0,{%1,%2};" : "=l"(r) : "f"(x), "f"(y)); return r;
}
__device__ __forceinline__ float hadd2(ull v) { float2 f = u2f2(v); return f.x + f.y; }

__device__ __forceinline__ float fast_gelu(float x) {
    float y  = x * 0.70710678118654752f;
    float ax = fabsf(y);
    float t  = __fdividef(1.0f, fmaf(0.3275911f, ax, 1.0f));
    float p  = fmaf(t, 1.061405429f, -1.453152027f);
    p = fmaf(t, p, 1.421413741f);
    p = fmaf(t, p, -0.284496736f);
    p = fmaf(t, p, 0.254829592f);
    p *= t;
    float e = __expf(-ax * ax);
    float erfv = copysignf(fmaf(-p, e, 1.0f), y);
    return 0.5f * x * (1.0f + erfv);
}

__device__ __forceinline__ void decode_tile(int t, int fastmode,
                                            int& b, int& rowi, int& j0, int& wrM) {
    if (fastmode) {
        if (t < NT_LL_FAST) {
            b = t / 640; int r = t - b * 640;
            if (r < 256) { rowi = r; j0 = r & 192; wrM = 0; }
            else {
                int r2 = r - 256; int pr = r2 >> 6;
                int br = (pr < 3) ? 0 : ((pr < 5) ? 1 : 2);
                int bc = (pr == 0) ? 1 : ((pr == 1 || pr == 3) ? 2 : 3);
                rowi = br * 64 + (r2 & 63); j0 = bc * 64; wrM = 1;
            }
        } else {
            int u = t - NT_LL_FAST; b = u / 3072; int r = u - b * 3072;
            rowi = LLEN + (r >> 2); j0 = (r & 3) << 6; wrM = 1;
        }
    } else {
        if (t < NT_LL_SLOW) {
            b = t >> 10; int r = t & 1023;
            rowi = r >> 2; j0 = (r & 3) << 6; wrM = 0;
        } else {
            int u = t - NT_LL_SLOW; b = u / 3072; int r = u - b * 3072;
            rowi = LLEN + (r >> 2); j0 = (r & 3) << 6; wrM = 1;
        }
    }
}

__device__ __forceinline__ float4 load_meta_fast(const float* pos,
                                                 float m0v, float b0v,
                                                 int b, int rowi, int j) {
    const float* pj = pos + ((size_t)b * NTOT + j) * 3;
    const float* pi = pos + ((size_t)b * NTOT + rowi) * 3;
    float d0 = pj[0] - pi[0];
    float d1 = pj[1] - pi[1];
    float d2 = pj[2] - pi[2];
    float d = 1.0f / (d0 * d0 + d1 * d1 + d2 * d2 + 1.0f);
    return make_float4(d0, d1, d2, m0v * d + b0v);
}

__device__ __forceinline__ float4 load_meta(const float* pos, const int* etype,
                                            const float* mw, const float* bw,
                                            int b, int rowi, int j) {
    const float* pj = pos + ((size_t)b * NTOT + j) * 3;
    const float* pi = pos + ((size_t)b * NTOT + rowi) * 3;
    float d0 = pj[0] - pi[0];
    float d1 = pj[1] - pi[1];
    float d2 = pj[2] - pi[2];
    float d = 1.0f / (d0 * d0 + d1 * d1 + d2 * d2 + 1.0f);
    int e = etype[((size_t)b * NTOT + rowi) * NTOT + j];
    return make_float4(d0, d1, d2, mw[e] * d + bw[e]);
}

__device__ __forceinline__ void compute_flags(int* ifl, const float* vb1,
                                              const float* stds, const float* mw,
                                              const float* bw, int nE, int tid, int nthr) {
    if (tid == 0) { ifl[0] = 1; ifl[1] = 1; ifl[2] = 1; }
    __syncthreads();
    if (tid < KDIM && vb1[tid] != 0.0f) atomicAnd(&ifl[0], 0);
    if (tid < KDIM) {
        float s = fabsf(stds[tid]) + 1e-5f;
        if (s < 0.004f) atomicAnd(&ifl[2], 0);
    }
    float m0v = mw[0], b0v = bw[0];
    for (int i = tid; i < nE; i += nthr)
        if (mw[i] != m0v || bw[i] != b0v) atomicAnd(&ifl[1], 0);
    __syncthreads();
}

// =====================  TABLE BUILD KERNEL  =====================
__global__ __launch_bounds__(512, 1)
void build_tab_kernel(const float* __restrict__ mw, const float* __restrict__ bw,
                      const float* __restrict__ means, const float* __restrict__ stds,
                      const float* __restrict__ ow1, const float* __restrict__ ob1,
                      const float* __restrict__ ow2, const float* __restrict__ vb1,
                      const float* __restrict__ vw1, const float* __restrict__ vw2,
                      int nE)
{
    extern __shared__ float sm[];
    const int tid = threadIdx.x;
    int* iflags = reinterpret_cast<int*>(sm + OFF_FLAG);
    compute_flags(iflags, vb1, stds, mw, bw, nE, tid, 512);
    const int fl = iflags[0] | (iflags[1] << 1) | (iflags[2] << 2);
    if (blockIdx.x == 0 && tid == 0) g_flags = fl;
    if (blockIdx.x == 0 && tid < 96) {
        int d = tid >> 5, h = tid & 31;
        float s = 0.0f;
        #pragma unroll 4
        for (int k = 0; k < KDIM; k++) s += vw1[d * KDIM + k] * vw2[k * HDIM + h];
        g_T3[d * 32 + h] = s;
    }
    if (fl != 7) return;

    for (int i = tid; i < 64 * 128; i += 512) {
        int kp = i >> 7, c = i & 127;
        sm[OFF_OW1 + kp * 256 + 2 * c]     = ow1[(2 * kp) * KDIM + c];
        sm[OFF_OW1 + kp * 256 + 2 * c + 1] = ow1[(2 * kp + 1) * KDIM + c];
    }
    for (int i = tid; i < 64 * 32; i += 512) {
        int kp = i >> 5, h = i & 31;
        sm[OFF_OW2 + kp * 64 + 2 * h]     = ow2[(2 * kp) * HDIM + h];
        sm[OFF_OW2 + kp * 64 + 2 * h + 1] = ow2[(2 * kp + 1) * HDIM + h];
    }
    if (tid < KDIM) {
        sm[OFF_OB1 + tid] = ob1[tid];
        float s  = fabsf(stds[tid]) + 1e-5f;
        float is = 1.0f / s;
        sm[OFF_MEAN + tid] = means[tid];
        sm[OFF_ISTD + tid] = is;
        sm[OFF_COEF + tid] = is * (1.0f / sqrtf(2.0f * 3.14159f));
    }
    __syncthreads();

    const float m0v = mw[0], b0v = bw[0];
    const float lo = fminf(b0v, m0v + b0v);
    const float span = fmaxf(b0v, m0v + b0v) - lo;
    const float step = span / (float)(TABN - 1);

    const int gm  = tid & 63;
    const int gkc = tid >> 6;
    const int s1_wid = tid >> 5, s1_lane = tid & 31;
    const int s1_wm = s1_wid & 3, s1_wn = s1_wid >> 2;
    const int s1_mg = s1_lane >> 3, s1_ng = s1_lane & 7;
    const int s1_mbase = s1_wm * 16 + s1_mg * 4;
    const int s1_cbase = s1_wn * 32;
    const int s1_npA   = s1_wn * 16 + s1_ng;
    const int s2_hg = (tid >> 5) & 3;
    const int s2_kh = (tid >> 7) & 1;
    const int s2_mh = tid >> 8;
    const int s2_h0 = s2_hg * 8;
    const int s2_m  = s2_mh * 32 + (tid & 31);

    for (int t = blockIdx.x; t < NTAB_TILES; t += gridDim.x) {
        {
            float x0 = lo + (float)(t * 64 + gm) * step;
            #pragma unroll
            for (int i = 0; i < 8; i++) {
                int kp = gkc * 8 + i;
                float2 mn = *reinterpret_cast<float2*>(sm + OFF_MEAN + 2 * kp);
                float2 is = *reinterpret_cast<float2*>(sm + OFF_ISTD + 2 * kp);
                float2 cf = *reinterpret_cast<float2*>(sm + OFF_COEF + 2 * kp);
                float tx = (x0 - mn.x) * is.x;
                float ty = (x0 - mn.y) * is.y;
                float2 g = make_float2(__expf(-0.5f * tx * tx) * cf.x,
                                       __expf(-0.5f * ty * ty) * cf.y);
                *reinterpret_cast<float2*>(sm + OFF_GP + kp * PP + 2 * gm) = g;
            }
        }
        __syncthreads();
        {
            ull acc[4][4];
            #pragma unroll
            for (int r = 0; r < 4; r++)
                #pragma unroll
                for (int j = 0; j < 4; j++) acc[r][j] = 0ull;
            const float* gpB = sm + OFF_GP + 2 * s1_mbase;
            const float* w1B = sm + OFF_OW1 + 2 * s1_cbase + 4 * s1_ng;
            #pragma unroll 4
            for (int kp = 0; kp < 64; kp++) {
                ulonglong2 g01 = *reinterpret_cast<const ulonglong2*>(gpB + kp * PP);
                ulonglong2 g23 = *reinterpret_cast<const ulonglong2*>(gpB + kp * PP + 4);
                ulonglong2 wA  = *reinterpret_cast<const ulonglong2*>(w1B + kp * 256);
                ulonglong2 wB  = *reinterpret_cast<const ulonglong2*>(w1B + kp * 256 + 32);
                acc[0][0] = ffma2(g01.x, wA.x, acc[0][0]);
                acc[0][1] = ffma2(g01.x, wA.y, acc[0][1]);
                acc[0][2] = ffma2(g01.x, wB.x, acc[0][2]);
                acc[0][3] = ffma2(g01.x, wB.y, acc[0][3]);
                acc[1][0] = ffma2(g01.y, wA.x, acc[1][0]);
                acc[1][1] = ffma2(g01.y, wA.y, acc[1][1]);
                acc[1][2] = ffma2(g01.y, wB.x, acc[1][2]);
                acc[1][3] = ffma2(g01.y, wB.y, acc[1][3]);
                acc[2][0] = ffma2(g23.x, wA.x, acc[2][0]);
                acc[2][1] = ffma2(g23.x, wA.y, acc[2][1]);
                acc[2][2] = ffma2(g23.x, wB.x, acc[2][2]);
                acc[2][3] = ffma2(g23.x, wB.y, acc[2][3]);
                acc[3][0] = ffma2(g23.y, wA.x, acc[3][0]);
                acc[3][1] = ffma2(g23.y, wA.y, acc[3][1]);
                acc[3][2] = ffma2(g23.y, wB.x, acc[3][2]);
                acc[3][3] = ffma2(g23.y, wB.y, acc[3][3]);
            }
            float2 obA = *reinterpret_cast<float2*>(sm + OFF_OB1 + s1_cbase + 2 * s1_ng);
            float2 obB = *reinterpret_cast<float2*>(sm + OFF_OB1 + s1_cbase + 2 * s1_ng + 16);
            #pragma unroll
            for (int r = 0; r < 4; r++) {
                int m = s1_mbase + r;
                float2 hA = make_float2(fast_gelu(hadd2(acc[r][0]) + obA.x),
                                        fast_gelu(hadd2(acc[r][1]) + obA.y));
                float2 hB = make_float2(fast_gelu(hadd2(acc[r][2]) + obB.x),
                                        fast_gelu(hadd2(acc[r][3]) + obB.y));
                *reinterpret_cast<float2*>(sm + OFF_H1P + s1_npA * PP + 2 * m) = hA;
                *reinterpret_cast<float2*>(sm + OFF_H1P + (s1_npA + 8) * PP + 2 * m) = hB;
            }
        }
        __syncthreads();
        float rowv[8];
        {
            const float* hB = sm + OFF_H1P + s2_kh * 32 * PP + 2 * s2_m;
            const float* oB = sm + OFF_OW2 + s2_kh * 2048 + 2 * s2_h0;
            ull R[8];
            #pragma unroll
            for (int j = 0; j < 8; j++) R[j] = 0ull;
            #pragma unroll 4
            for (int i = 0; i < 32; i++) {
                ull hp = *reinterpret_cast<const ull*>(hB + i * PP);
                ulonglong2 o01 = *reinterpret_cast<const ulonglong2*>(oB + i * 64);
                ulonglong2 o23 = *reinterpret_cast<const ulonglong2*>(oB + i * 64 + 4);
                ulonglong2 o45 = *reinterpret_cast<const ulonglong2*>(oB + i * 64 + 8);
                ulonglong2 o67 = *reinterpret_cast<const ulonglong2*>(oB + i * 64 + 12);
                R[0] = ffma2(hp, o01.x, R[0]); R[1] = ffma2(hp, o01.y, R[1]);
                R[2] = ffma2(hp, o23.x, R[2]); R[3] = ffma2(hp, o23.y, R[3]);
                R[4] = ffma2(hp, o45.x, R[4]); R[5] = ffma2(hp, o45.y, R[5]);
                R[6] = ffma2(hp, o67.x, R[6]); R[7] = ffma2(hp, o67.y, R[7]);
            }
            #pragma unroll
            for (int j = 0; j < 8; j++) rowv[j] = hadd2(R[j]);
        }
        if (s2_kh) {
            float* sc = sm + OFF_SCR + s2_m * SCP + s2_h0;
            *reinterpret_cast<float4*>(sc)     = make_float4(rowv[0], rowv[1], rowv[2], rowv[3]);
            *reinterpret_cast<float4*>(sc + 4) = make_float4(rowv[4], rowv[5], rowv[6], rowv[7]);
        }
        __syncthreads();
        if (s2_kh == 0) {
            const float* sc = sm + OFF_SCR + s2_m * SCP + s2_h0;
            float4 r0 = *reinterpret_cast<const float4*>(sc);
            float4 r1 = *reinterpret_cast<const float4*>(sc + 4);
            int row = t * 64 + s2_m;
            float4 w0 = make_float4(rowv[0] + r0.x, rowv[1] + r0.y,
                                    rowv[2] + r0.z, rowv[3] + r0.w);
            float4 w1 = make_float4(rowv[4] + r1.x, rowv[5] + r1.y,
                                    rowv[6] + r1.z, rowv[7] + r1.w);
            *reinterpret_cast<float4*>(g_tab + (size_t)row * HDIM + s2_h0)     = w0;
            *reinterpret_cast<float4*>(g_tab + (size_t)row * HDIM + s2_h0 + 4) = w1;
        }
        __syncthreads();
    }
}

// =====================  FAST KERNEL (1 barrier/tile, no scratch)  ==============
__global__ __launch_bounds__(512, 2)
void fast_tab_kernel(
    const float* __restrict__ pos,
    const float* __restrict__ mw,
    const float* __restrict__ bw,
    const float* __restrict__ ob2,
    const float* __restrict__ vw1,
    const float* __restrict__ vw2,
    const float* __restrict__ vb2,
    float* __restrict__ out)
{
    extern __shared__ float sm[];
    const int tid = threadIdx.x;
    if (g_flags != 7) return;

    for (int i = tid; i < 64 * 32; i += 512) {
        int kp = i >> 5, h = i & 31;
        sm[F_VW2 + kp * 64 + 2 * h]     = vw2[(2 * kp) * HDIM + h];
        sm[F_VW2 + kp * 64 + 2 * h + 1] = vw2[(2 * kp + 1) * HDIM + h];
    }
    if (tid < 3 * KDIM) sm[F_VW1 + tid] = vw1[tid];
    if (tid < HDIM) sm[F_B2 + tid] = ob2[tid] + vb2[tid];

    const float m0v = mw[0], b0v = bw[0];
    const float lo = fminf(b0v, m0v + b0v);
    const float span = fmaxf(b0v, m0v + b0v) - lo;
    const float invd = (span > 0.0f) ? (float)(TABN - 1) / span : 0.0f;

    const int gm  = tid & 63;        // edge m (v1 + S2' share this)
    const int gkc = tid >> 6;        // v1: kp chunk; S2': h quad
    const int s2_h0 = gkc * 4;

    {
        int b0, ri0, j00, w0;
        decode_tile((int)blockIdx.x, 1, b0, ri0, j00, w0);
        if ((int)blockIdx.x < NTILES_FAST && tid < 64) {
            float4 m = load_meta_fast(pos, m0v, b0v, b0, ri0, j00 + tid);
            *reinterpret_cast<float4*>(sm + F_DLM4 + tid * 4) = m;
        }
    }
    __syncthreads();

    int cur = 0, zi = 0;
    for (int t = blockIdx.x; t < NTILES_FAST; t += gridDim.x, zi++) {
        int b, rowi, j0, wrM;
        decode_tile(t, 1, b, rowi, j0, wrM);

        if (zi < NZIF) {
            #pragma unroll
            for (int zz = 0; zz < 3; zz++) {
                int idx = ((zi * 3 + zz) * GRIDF + (int)blockIdx.x) * 512 + tid;
                if (idx < ZTOT_F4) {
                    int jq = idx % 192;
                    int r  = idx / 192;
                    int ip = r % 768;
                    int bhh = r / 768;
                    size_t addr = (((size_t)bhh << 10) + 256 + ip) * 1024 + 256 + 4 * jq;
                    *reinterpret_cast<float4*>(out + addr) = make_float4(0.f, 0.f, 0.f, 0.f);
                }
            }
        }

        const int tn = t + gridDim.x;
        float4 pf;
        const bool havePf = (tn < NTILES_FAST) && (tid < 64);
        if (havePf) {
            int bn, rin, j0n, wn;
            decode_tile(tn, 1, bn, rin, j0n, wn);
            pf = load_meta_fast(pos, m0v, b0v, bn, rin, j0n + tid);
        }

        // v1 phase -> VP1[cur]
        {
            float4 dm = *reinterpret_cast<float4*>(sm + F_DLM4 + cur * 256 + gm * 4);
            float* vp1 = sm + F_VP1 + cur * (64 * PP);
            #pragma unroll
            for (int i = 0; i < 8; i++) {
                int kp = gkc * 8 + i;
                float2 w0 = *reinterpret_cast<float2*>(sm + F_VW1 + 2 * kp);
                float2 w1 = *reinterpret_cast<float2*>(sm + F_VW1 + 128 + 2 * kp);
                float2 w2 = *reinterpret_cast<float2*>(sm + F_VW1 + 256 + 2 * kp);
                float sx = dm.x * w0.x + dm.y * w1.x + dm.z * w2.x;   // vb1 == 0
                float sy = dm.x * w0.y + dm.y * w1.y + dm.z * w2.y;
                float2 v1 = make_float2(fast_gelu(sx), fast_gelu(sy));
                *reinterpret_cast<float2*>(vp1 + kp * PP + 2 * gm) = v1;
            }
        }
        if (havePf)
            *reinterpret_cast<float4*>(sm + F_DLM4 + (cur ^ 1) * 256 + tid * 4) = pf;

        // table lerp hoisted pre-barrier (L2 latency drains under the wait)
        float eft[4];
        {
            float x0 = sm[F_DLM4 + cur * 256 + gm * 4 + 3];
            float u = (x0 - lo) * invd;
            u = fminf(fmaxf(u, 0.0f), (float)(TABN - 1));
            int i0 = (int)u;
            if (i0 > TABN - 2) i0 = TABN - 2;
            float f = u - (float)i0;
            const float* r0 = g_tab + (size_t)i0 * HDIM + s2_h0;
            float4 a0 = *reinterpret_cast<const float4*>(r0);
            float4 c0 = *reinterpret_cast<const float4*>(r0 + HDIM);
            eft[0] = fmaf(f, c0.x - a0.x, a0.x);
            eft[1] = fmaf(f, c0.y - a0.y, a0.y);
            eft[2] = fmaf(f, c0.z - a0.z, a0.z);
            eft[3] = fmaf(f, c0.w - a0.w, a0.w);
        }
        __syncthreads();   // (A) — the only per-tile barrier

        // S2': va over full K; 1 m x 4 h per thread; no reduction needed
        {
            const float* vB = sm + F_VP1 + cur * (64 * PP) + 2 * gm;
            const float* wB = sm + F_VW2 + 2 * s2_h0;
            ull A0 = 0, A1 = 0, A2 = 0, A3 = 0;
            #pragma unroll 4
            for (int kp = 0; kp < 64; kp++) {
                ull vp = *reinterpret_cast<const ull*>(vB + kp * PP);
                ulonglong2 wab = *reinterpret_cast<const ulonglong2*>(wB + kp * 64);
                ulonglong2 wcd = *reinterpret_cast<const ulonglong2*>(wB + kp * 64 + 4);
                A0 = ffma2(vp, wab.x, A0);
                A1 = ffma2(vp, wab.y, A1);
                A2 = ffma2(vp, wcd.x, A2);
                A3 = ffma2(vp, wcd.y, A3);
            }
            const size_t bh = (size_t)b * HDIM;
            const size_t rb = ((bh + s2_h0) * NTOT + rowi) * NTOT + j0 + gm;
            out[rb]                              = hadd2(A0) + eft[0] + sm[F_B2 + s2_h0];
            out[rb + (size_t)NTOT * NTOT]        = hadd2(A1) + eft[1] + sm[F_B2 + s2_h0 + 1];
            out[rb + 2 * (size_t)NTOT * NTOT]    = hadd2(A2) + eft[2] + sm[F_B2 + s2_h0 + 2];
            out[rb + 3 * (size_t)NTOT * NTOT]    = hadd2(A3) + eft[3] + sm[F_B2 + s2_h0 + 3];
        }
        cur ^= 1;
        // VP1[cur^1] (just used) is overwritten two tiles from now, which is
        // after the NEXT tile's barrier (A) — every warp has finished this
        // tile's S2' reads by then.
    }
}

// ============  MIRROR TRANSPOSE KERNEL (coalesced col-slab writes)  ============
__global__ __launch_bounds__(256)
void mirror_transpose_kernel(
    const float* __restrict__ pos,
    float* __restrict__ out)
{
    __shared__ float tile[32 * 33];
    __shared__ float pjv[32 * 3];
    __shared__ float piv[32 * 3];
    const int tid = threadIdx.x;
    if (g_flags != 7) return;

    int tt = (int)blockIdx.x % NTT_PER_BH;
    int bh = (int)blockIdx.x / NTT_PER_BH;
    int h = bh & 31, b = bh >> 5;
    int i0, j0;
    if (tt < 192) {
        int it = tt % 24, jt = tt / 24;
        i0 = 256 + it * 32; j0 = jt * 32;
    } else {
        int u = tt - 192;
        int p = u >> 2, si = (u >> 1) & 1, sj = u & 1;
        const int brt[6] = {0, 0, 0, 1, 1, 2};
        const int bct[6] = {1, 2, 3, 2, 3, 3};
        i0 = brt[p] * 64 + si * 32;
        j0 = bct[p] * 64 + sj * 32;
    }

    const float t3x = g_T3[h], t3y = g_T3[32 + h], t3z = g_T3[64 + h];

    if (tid < 32) {
        const float* p3 = pos + ((size_t)b * NTOT + j0 + tid) * 3;
        pjv[tid * 3] = p3[0]; pjv[tid * 3 + 1] = p3[1]; pjv[tid * 3 + 2] = p3[2];
    } else if (tid < 64) {
        int l = tid - 32;
        const float* p3 = pos + ((size_t)b * NTOT + i0 + l) * 3;
        piv[l * 3] = p3[0]; piv[l * 3 + 1] = p3[1]; piv[l * 3 + 2] = p3[2];
    }

    const int wy = tid >> 5, lane = tid & 31;
    const size_t base = (size_t)bh * NTOT * NTOT;
    #pragma unroll
    for (int r = 0; r < 4; r++) {
        int il = wy + 8 * r;
        tile[il * 33 + lane] = out[base + (size_t)(i0 + il) * NTOT + j0 + lane];
    }
    __syncthreads();
    #pragma unroll
    for (int r = 0; r < 4; r++) {
        int jl = wy + 8 * r;
        float v = tile[lane * 33 + jl];
        float d0 = pjv[jl * 3]     - piv[lane * 3];
        float d1 = pjv[jl * 3 + 1] - piv[lane * 3 + 1];
        float d2 = pjv[jl * 3 + 2] - piv[lane * 3 + 2];
        float corr = d0 * t3x + d1 * t3y + d2 * t3z;
        out[base + (size_t)(j0 + jl) * NTOT + i0 + lane] = v - corr;
    }
}

// =====================  EXACT KERNEL (fallback)  ================================
__global__ __launch_bounds__(512, 1)
void fused_distbias_kernel(
    const float* __restrict__ pos,
    const int*   __restrict__ etype,
    const float* __restrict__ mw,
    const float* __restrict__ bw,
    const float* __restrict__ means,
    const float* __restrict__ stds,
    const float* __restrict__ ow1,
    const float* __restrict__ ob1,
    const float* __restrict__ ow2,
    const float* __restrict__ ob2,
    const float* __restrict__ vw1,
    const float* __restrict__ vb1,
    const float* __restrict__ vw2,
    const float* __restrict__ vb2,
    float* __restrict__ out)
{
    extern __shared__ float sm[];
    const int tid = threadIdx.x;
    const int fl = g_flags;
    if (fl == 7) return;
    const int vbzero = fl & 1;
    const int fastmode = (fl & 3) == 3;
    const int ntiles = fastmode ? NTILES_FAST : NTILES_SLOW;

    for (int i = tid; i < 64 * 128; i += 512) {
        int kp = i >> 7, c = i & 127;
        sm[OFF_OW1 + kp * 256 + 2 * c]     = ow1[(2 * kp) * KDIM + c];
        sm[OFF_OW1 + kp * 256 + 2 * c + 1] = ow1[(2 * kp + 1) * KDIM + c];
    }
    for (int i = tid; i < 64 * 32; i += 512) {
        int kp = i >> 5, h = i & 31;
        sm[OFF_OW2 + kp * 64 + 2 * h]     = ow2[(2 * kp) * HDIM + h];
        sm[OFF_OW2 + kp * 64 + 2 * h + 1] = ow2[(2 * kp + 1) * HDIM + h];
        sm[OFF_VW2 + kp * 64 + 2 * h]     = vw2[(2 * kp) * HDIM + h];
        sm[OFF_VW2 + kp * 64 + 2 * h + 1] = vw2[(2 * kp + 1) * HDIM + h];
    }
    if (tid < 3 * KDIM) sm[OFF_VW1 + tid] = vw1[tid];
    if (tid < KDIM) {
        sm[OFF_VB1 + tid] = vb1[tid];
        sm[OFF_OB1 + tid] = ob1[tid];
        float s  = fabsf(stds[tid]) + 1e-5f;
        float is = 1.0f / s;
        sm[OFF_MEAN + tid] = means[tid];
        sm[OFF_ISTD + tid] = is;
        sm[OFF_COEF + tid] = is * (1.0f / sqrtf(2.0f * 3.14159f));
    }
    if (tid < HDIM) sm[OFF_B2 + tid] = ob2[tid] + vb2[tid];
    if (tid < 96) sm[OFF_TVV + tid] = g_T3[tid];
    __syncthreads();

    const int gm  = tid & 63;
    const int gkc = tid >> 6;
    const int s1_wid = tid >> 5, s1_lane = tid & 31;
    const int s1_wm = s1_wid & 3, s1_wn = s1_wid >> 2;
    const int s1_mg = s1_lane >> 3, s1_ng = s1_lane & 7;
    const int s1_mbase = s1_wm * 16 + s1_mg * 4;
    const int s1_cbase = s1_wn * 32;
    const int s1_npA   = s1_wn * 16 + s1_ng;
    const int s2_hg = (tid >> 5) & 3;
    const int s2_kh = (tid >> 7) & 1;
    const int s2_mh = tid >> 8;
    const int s2_h0 = s2_hg * 8;
    const int s2_m  = s2_mh * 32 + (tid & 31);

    {
        int b0, ri0, j00, w0;
        decode_tile((int)blockIdx.x, fastmode, b0, ri0, j00, w0);
        if ((int)blockIdx.x < ntiles && tid < 64) {
            float4 m = load_meta(pos, etype, mw, bw, b0, ri0, j00 + tid);
            *reinterpret_cast<float4*>(sm + OFF_DLM4 + tid * 4) = m;
        }
    }
    __syncthreads();

    int cur = 0, zi = 0;
    for (int t = blockIdx.x; t < ntiles; t += gridDim.x, zi++) {
        int b, rowi, j0, wrM;
        decode_tile(t, fastmode, b, rowi, j0, wrM);

        if (zi < NZI) {
            #pragma unroll
            for (int zz = 0; zz < 3; zz++) {
                int idx = ((zi * 3 + zz) * GRIDX + (int)blockIdx.x) * 512 + tid;
                if (idx < ZTOT_F4) {
                    int jq = idx % 192;
                    int r  = idx / 192;
                    int ip = r % 768;
                    int bhh = r / 768;
                    size_t addr = (((size_t)bhh << 10) + 256 + ip) * 1024 + 256 + 4 * jq;
                    *reinterpret_cast<float4*>(out + addr) = make_float4(0.f, 0.f, 0.f, 0.f);
                }
            }
        }

        const int tn = t + gridDim.x;
        float4 pf;
        const bool havePf = (tn < ntiles) && (tid < 64);
        if (havePf) {
            int bn, rin, j0n, wn;
            decode_tile(tn, fastmode, bn, rin, j0n, wn);
            pf = load_meta(pos, etype, mw, bw, bn, rin, j0n + tid);
        }

        {
            float4 dm = *reinterpret_cast<float4*>(sm + OFF_DLM4 + cur * 256 + gm * 4);
            #pragma unroll
            for (int i = 0; i < 8; i++) {
                int kp = gkc * 8 + i;
                float2 mn = *reinterpret_cast<float2*>(sm + OFF_MEAN + 2 * kp);
                float2 is = *reinterpret_cast<float2*>(sm + OFF_ISTD + 2 * kp);
                float2 cf = *reinterpret_cast<float2*>(sm + OFF_COEF + 2 * kp);
                float2 w0 = *reinterpret_cast<float2*>(sm + OFF_VW1 + 2 * kp);
                float2 w1 = *reinterpret_cast<float2*>(sm + OFF_VW1 + 128 + 2 * kp);
                float2 w2 = *reinterpret_cast<float2*>(sm + OFF_VW1 + 256 + 2 * kp);
                float2 vb = *reinterpret_cast<float2*>(sm + OFF_VB1 + 2 * kp);
                float tx = (dm.w - mn.x) * is.x;
                float ty = (dm.w - mn.y) * is.y;
                float2 g = make_float2(__expf(-0.5f * tx * tx) * cf.x,
                                       __expf(-0.5f * ty * ty) * cf.y);
                float sx = dm.x * w0.x + dm.y * w1.x + dm.z * w2.x + vb.x;
                float sy = dm.x * w0.y + dm.y * w1.y + dm.z * w2.y + vb.y;
                float2 v1 = make_float2(fast_gelu(sx), fast_gelu(sy));
                *reinterpret_cast<float2*>(sm + OFF_GP  + kp * PP + 2 * gm) = g;
                *reinterpret_cast<float2*>(sm + OFF_VP1 + kp * PP + 2 * gm) = v1;
            }
        }
        if (havePf)
            *reinterpret_cast<float4*>(sm + OFF_DLM4 + (cur ^ 1) * 256 + tid * 4) = pf;
        __syncthreads();

        {
            ull acc[4][4];
            #pragma unroll
            for (int r = 0; r < 4; r++)
                #pragma unroll
                for (int j = 0; j < 4; j++) acc[r][j] = 0ull;
            const float* gpB = sm + OFF_GP + 2 * s1_mbase;
            const float* w1B = sm + OFF_OW1 + 2 * s1_cbase + 4 * s1_ng;
            #pragma unroll 4
            for (int kp = 0; kp < 64; kp++) {
                ulonglong2 g01 = *reinterpret_cast<const ulonglong2*>(gpB + kp * PP);
                ulonglong2 g23 = *reinterpret_cast<const ulonglong2*>(gpB + kp * PP + 4);
                ulonglong2 wA  = *reinterpret_cast<const ulonglong2*>(w1B + kp * 256);
                ulonglong2 wB  = *reinterpret_cast<const ulonglong2*>(w1B + kp * 256 + 32);
                acc[0][0] = ffma2(g01.x, wA.x, acc[0][0]);
                acc[0][1] = ffma2(g01.x, wA.y, acc[0][1]);
                acc[0][2] = ffma2(g01.x, wB.x, acc[0][2]);
                acc[0][3] = ffma2(g01.x, wB.y, acc[0][3]);
                acc[1][0] = ffma2(g01.y, wA.x, acc[1][0]);
                acc[1][1] = ffma2(g01.y, wA.y, acc[1][1]);
                acc[1][2] = ffma2(g01.y, wB.x, acc[1][2]);
                acc[1][3] = ffma2(g01.y, wB.y, acc[1][3]);
                acc[2][0] = ffma2(g23.x, wA.x, acc[2][0]);
                acc[2][1] = ffma2(g23.x, wA.y, acc[2][1]);
                acc[2][2] = ffma2(g23.x, wB.x, acc[2][2]);
                acc[2][3] = ffma2(g23.x, wB.y, acc[2][3]);
                acc[3][0] = ffma2(g23.y, wA.x, acc[3][0]);
                acc[3][1] = ffma2(g23.y, wA.y, acc[3][1]);
                acc[3][2] = ffma2(g23.y, wB.x, acc[3][2]);
                acc[3][3] = ffma2(g23.y, wB.y, acc[3][3]);
            }
            float2 obA = *reinterpret_cast<float2*>(sm + OFF_OB1 + s1_cbase + 2 * s1_ng);
            float2 obB = *reinterpret_cast<float2*>(sm + OFF_OB1 + s1_cbase + 2 * s1_ng + 16);
            #pragma unroll
            for (int r = 0; r < 4; r++) {
                int m = s1_mbase + r;
                float2 hA = make_float2(fast_gelu(hadd2(acc[r][0]) + obA.x),
                                        fast_gelu(hadd2(acc[r][1]) + obA.y));
                float2 hB = make_float2(fast_gelu(hadd2(acc[r][2]) + obB.x),
                                        fast_gelu(hadd2(acc[r][3]) + obB.y));
                *reinterpret_cast<float2*>(sm + OFF_H1P + s1_npA * PP + 2 * m) = hA;
                *reinterpret_cast<float2*>(sm + OFF_H1P + (s1_npA + 8) * PP + 2 * m) = hB;
            }
        }
        __syncthreads();

        float rowv[8];
        {
            const float* hB = sm + OFF_H1P + s2_kh * 32 * PP + 2 * s2_m;
            const float* vB = sm + OFF_VP1 + s2_kh * 32 * PP + 2 * s2_m;
            const float* oB = sm + OFF_OW2 + s2_kh * 2048 + 2 * s2_h0;
            const float* wB = sm + OFF_VW2 + s2_kh * 2048 + 2 * s2_h0;
            ull R[8];
            #pragma unroll
            for (int j = 0; j < 8; j++) R[j] = 0ull;
            #pragma unroll 4
            for (int i = 0; i < 32; i++) {
                ull hp = *reinterpret_cast<const ull*>(hB + i * PP);
                ull vp = *reinterpret_cast<const ull*>(vB + i * PP);
                ulonglong2 o01 = *reinterpret_cast<const ulonglong2*>(oB + i * 64);
                ulonglong2 o23 = *reinterpret_cast<const ulonglong2*>(oB + i * 64 + 4);
                ulonglong2 o45 = *reinterpret_cast<const ulonglong2*>(oB + i * 64 + 8);
                ulonglong2 o67 = *reinterpret_cast<const ulonglong2*>(oB + i * 64 + 12);
                R[0] = ffma2(hp, o01.x, R[0]); R[1] = ffma2(hp, o01.y, R[1]);
                R[2] = ffma2(hp, o23.x, R[2]); R[3] = ffma2(hp, o23.y, R[3]);
                R[4] = ffma2(hp, o45.x, R[4]); R[5] = ffma2(hp, o45.y, R[5]);
                R[6] = ffma2(hp, o67.x, R[6]); R[7] = ffma2(hp, o67.y, R[7]);
                ulonglong2 v01 = *reinterpret_cast<const ulonglong2*>(wB + i * 64);
                ulonglong2 v23 = *reinterpret_cast<const ulonglong2*>(wB + i * 64 + 4);
                ulonglong2 v45 = *reinterpret_cast<const ulonglong2*>(wB + i * 64 + 8);
                ulonglong2 v67 = *reinterpret_cast<const ulonglong2*>(wB + i * 64 + 12);
                R[0] = ffma2(vp, v01.x, R[0]); R[1] = ffma2(vp, v01.y, R[1]);
                R[2] = ffma2(vp, v23.x, R[2]); R[3] = ffma2(vp, v23.y, R[3]);
                R[4] = ffma2(vp, v45.x, R[4]); R[5] = ffma2(vp, v45.y, R[5]);
                R[6] = ffma2(vp, v67.x, R[6]); R[7] = ffma2(vp, v67.y, R[7]);
            }
            #pragma unroll
            for (int j = 0; j < 8; j++) rowv[j] = hadd2(R[j]);
        }
        float corr[8];
        if (wrM && vbzero && s2_kh == 0) {
            float4 dmv = *reinterpret_cast<float4*>(sm + OFF_DLM4 + cur * 256 + s2_m * 4);
            #pragma unroll
            for (int j = 0; j < 8; j++) {
                int h = s2_h0 + j;
                corr[j] = dmv.x * sm[OFF_TVV + h]
                        + dmv.y * sm[OFF_TVV + 32 + h]
                        + dmv.z * sm[OFF_TVV + 64 + h];
            }
        }
        if (s2_kh) {
            float* sc = sm + OFF_SCR + s2_m * SCP + s2_h0;
            *reinterpret_cast<float4*>(sc)     = make_float4(rowv[0], rowv[1], rowv[2], rowv[3]);
            *reinterpret_cast<float4*>(sc + 4) = make_float4(rowv[4], rowv[5], rowv[6], rowv[7]);
        }
        __syncthreads();
        if (s2_kh == 0) {
            const float* sc = sm + OFF_SCR + s2_m * SCP + s2_h0;
            float4 r0 = *reinterpret_cast<const float4*>(sc);
            float4 r1 = *reinterpret_cast<const float4*>(sc + 4);
            rowv[0] += r0.x; rowv[1] += r0.y; rowv[2] += r0.z; rowv[3] += r0.w;
            rowv[4] += r1.x; rowv[5] += r1.y; rowv[6] += r1.z; rowv[7] += r1.w;
            const size_t bh = (size_t)b * HDIM;
            #pragma unroll
            for (int j = 0; j < 8; j++) {
                int h = s2_h0 + j;
                float v = rowv[j] + sm[OFF_B2 + h];
                out[((bh + h) * NTOT + rowi) * NTOT + j0 + s2_m] = v;
                if (wrM && vbzero)
                    out[((bh + h) * NTOT + (j0 + s2_m)) * NTOT + rowi] = v - corr[j];
            }
        }

        if (wrM && !vbzero) {
            float dp[8];
            {
                float4 dmv = *reinterpret_cast<float4*>(sm + OFF_DLM4 + cur * 256 + s2_m * 4);
                const float* vB = sm + OFF_VP1 + s2_kh * 32 * PP + 2 * s2_m;
                const float* wB = sm + OFF_VW2 + s2_kh * 2048 + 2 * s2_h0;
                ull D[8];
                #pragma unroll
                for (int j = 0; j < 8; j++) D[j] = 0ull;
                for (int i = 0; i < 32; i++) {
                    int kp = s2_kh * 32 + i;
                    float2 w0 = *reinterpret_cast<float2*>(sm + OFF_VW1 + 2 * kp);
                    float2 w1 = *reinterpret_cast<float2*>(sm + OFF_VW1 + 128 + 2 * kp);
                    float2 w2 = *reinterpret_cast<float2*>(sm + OFF_VW1 + 256 + 2 * kp);
                    float2 vb = *reinterpret_cast<float2*>(sm + OFF_VB1 + 2 * kp);
                    float sx = dmv.x * w0.x + dmv.y * w1.x + dmv.z * w2.x + vb.x;
                    float sy = dmv.x * w0.y + dmv.y * w1.y + dmv.z * w2.y + vb.y;
                    float2 pv = u2f2(*reinterpret_cast<const ull*>(vB + i * PP));
                    ull dq = f2pack(fast_gelu(2.0f * vb.x - sx) - pv.x,
                                    fast_gelu(2.0f * vb.y - sy) - pv.y);
                    ulonglong2 v01 = *reinterpret_cast<const ulonglong2*>(wB + i * 64);
                    ulonglong2 v23 = *reinterpret_cast<const ulonglong2*>(wB + i * 64 + 4);
                    ulonglong2 v45 = *reinterpret_cast<const ulonglong2*>(wB + i * 64 + 8);
                    ulonglong2 v67 = *reinterpret_cast<const ulonglong2*>(wB + i * 64 + 12);
                    D[0] = ffma2(dq, v01.x, D[0]); D[1] = ffma2(dq, v01.y, D[1]);
                    D[2] = ffma2(dq, v23.x, D[2]); D[3] = ffma2(dq, v23.y, D[3]);
                    D[4] = ffma2(dq, v45.x, D[4]); D[5] = ffma2(dq, v45.y, D[5]);
                    D[6] = ffma2(dq, v67.x, D[6]); D[7] = ffma2(dq, v67.y, D[7]);
                }
                #pragma unroll
                for (int j = 0; j < 8; j++) dp[j] = hadd2(D[j]);
            }
            __syncthreads();
            if (s2_kh) {
                float* sc = sm + OFF_SCR + s2_m * SCP + s2_h0;
                *reinterpret_cast<float4*>(sc)     = make_float4(dp[0], dp[1], dp[2], dp[3]);
                *reinterpret_cast<float4*>(sc + 4) = make_float4(dp[4], dp[5], dp[6], dp[7]);
            }
            __syncthreads();
            if (s2_kh == 0) {
                const float* sc = sm + OFF_SCR + s2_m * SCP + s2_h0;
                float4 r0 = *reinterpret_cast<const float4*>(sc);
                float4 r1 = *reinterpret_cast<const float4*>(sc + 4);
                dp[0] += r0.x; dp[1] += r0.y; dp[2] += r0.z; dp[3] += r0.w;
                dp[4] += r1.x; dp[5] += r1.y; dp[6] += r1.z; dp[7] += r1.w;
                const size_t bh = (size_t)b * HDIM;
                #pragma unroll
                for (int j = 0; j < 8; j++) {
                    int h = s2_h0 + j;
                    float v = rowv[j] + dp[j] + sm[OFF_B2 + h];
                    out[((bh + h) * NTOT + (j0 + s2_m)) * NTOT + rowi] = v;
                }
            }
        }
        cur ^= 1;
    }
}

extern "C" void kernel_launch(void* const* d_in, const int* in_sizes, int n_in,
                              void* d_out, int out_size) {
    const float* pos    = (const float*)d_in[0];
    const int*   etype  = (const int*)d_in[1];
    const float* means  = (const float*)d_in[3];
    const float* stds   = (const float*)d_in[4];
    const float* mul_w  = (const float*)d_in[5];
    const float* bias_w = (const float*)d_in[6];
    const float* ow1    = (const float*)d_in[7];
    const float* ob1    = (const float*)d_in[8];
    const float* ow2    = (const float*)d_in[9];
    const float* ob2    = (const float*)d_in[10];
    const float* vw1    = (const float*)d_in[11];
    const float* vb1    = (const float*)d_in[12];
    const float* vw2    = (const float*)d_in[13];
    const float* vb2    = (const float*)d_in[14];
    float* out = (float*)d_out;
    int nE = in_sizes[5];

    cudaFuncSetAttribute(build_tab_kernel,
                         cudaFuncAttributeMaxDynamicSharedMemorySize, SMEM_BYTES);
    cudaFuncSetAttribute(fast_tab_kernel,
                         cudaFuncAttributeMaxDynamicSharedMemorySize, FSMEM_BYTES);
    cudaFuncSetAttribute(fused_distbias_kernel,
                         cudaFuncAttributeMaxDynamicSharedMemorySize, SMEM_BYTES);

    build_tab_kernel<<<GRIDX, 512, SMEM_BYTES>>>(
        mul_w, bias_w, means, stds, ow1, ob1, ow2, vb1, vw1, vw2, nE);

    fast_tab_kernel<<<GRIDF, 512, FSMEM_BYTES>>>(
        pos, mul_w, bias_w, ob2, vw1, vw2, vb2, out);

    mirror_transpose_kernel<<<NTT_TOTAL, 256>>>(pos, out);

    fused_distbias_kernel<<<GRIDX, 512, SMEM_BYTES>>>(
        pos, etype, mul_w, bias_w, means, stds,
        ow1, ob1, ow2, ob2, vw1, vb1, vw2, vb2, out);
}